// round 8
// baseline (speedup 1.0000x reference)
#include <cuda_runtime.h>
#include <math.h>

#define BATCH 16
#define CH    512
#define HW    1024
#define NH    8
#define HD    64
#define NG    8
#define EPSV  1e-5f

// Scratch (allocation-free rule: __device__ globals)
__device__ float g_qkv [BATCH * 3 * CH * HW];      // 100.7 MB
__device__ float g_atto[BATCH * CH * HW];          // 33.5 MB
__device__ float g_sc  [BATCH * CH];               // per-(b,c) GN scale
__device__ float g_sh  [BATCH * CH];               // per-(b,c) GN shift

// ---------------------------------------------------------------------------
// GroupNorm stats only: one CTA per (b, g). Writes per-channel scale/shift.
// ---------------------------------------------------------------------------
__global__ void gn_stats(const float* __restrict__ x,
                         const float* __restrict__ w,
                         const float* __restrict__ bias) {
    const int GROUP = (CH / NG) * HW;   // 65536
    int bg = blockIdx.x;
    int b = bg / NG, g = bg % NG;
    const float* xp = x + (size_t)b * CH * HW + (size_t)g * (CH / NG) * HW;
    int tid = threadIdx.x;

    float s = 0.f, s2 = 0.f;
    for (int i = tid * 4; i < GROUP; i += blockDim.x * 4) {
        float4 v = *(const float4*)(xp + i);
        s  += v.x + v.y + v.z + v.w;
        s2 += v.x * v.x + v.y * v.y + v.z * v.z + v.w * v.w;
    }
    __shared__ float rs[256], rs2[256];
    rs[tid] = s; rs2[tid] = s2;
    __syncthreads();
    for (int o = 128; o > 0; o >>= 1) {
        if (tid < o) { rs[tid] += rs[tid + o]; rs2[tid] += rs2[tid + o]; }
        __syncthreads();
    }
    float mu  = rs[0]  * (1.0f / GROUP);
    float var = rs2[0] * (1.0f / GROUP) - mu * mu;
    float inv = rsqrtf(var + EPSV);

    if (tid < CH / NG) {
        int c = g * (CH / NG) + tid;
        float sc = w[c] * inv;
        g_sc[b * CH + c] = sc;
        g_sh[b * CH + c] = bias[c] - mu * sc;
    }
}

// ---------------------------------------------------------------------------
// QKV GEMM with fused GroupNorm on the B operand, 2-stage smem pipeline:
//   qkv[b][o][i] = sum_k W[o][k] * (x[b][k][i]*sc[b][k]+sh[b][k]) + bq[o]
// M=1536, N=1024, K=512 per batch. Tile 128x64x16, 8x4 per thread, 256 thr.
// ---------------------------------------------------------------------------
__global__ void qkv_gemm(const float* __restrict__ x,
                         const float* __restrict__ Wq,
                         const float* __restrict__ bq) {
    int b  = blockIdx.z;
    int o0 = blockIdx.y * 128;
    int i0 = blockIdx.x * 64;
    const float* X = x     + (size_t)b * CH * HW;
    float*       Y = g_qkv + (size_t)b * 3 * CH * HW;

    __shared__ float As[2][16][132];   // [stage][k][o]
    __shared__ float Bs[2][16][64];    // [stage][k][i]

    int tid = threadIdx.x;
    int tx = tid & 15, ty = tid >> 4;
    int ar = tid >> 1;                 // A-row this thread loads
    int ak = (tid & 1) * 8;            // A k-offset
    int br = tid >> 4;                 // B k-row this thread loads
    int bc = (tid & 15) * 4;           // B col
    float acc[8][4] = {};

    // prologue: stage 0
    {
        float4 a0 = *(const float4*)(Wq + (size_t)(o0 + ar) * CH + ak);
        float4 a1 = *(const float4*)(Wq + (size_t)(o0 + ar) * CH + ak + 4);
        As[0][ak + 0][ar] = a0.x; As[0][ak + 1][ar] = a0.y;
        As[0][ak + 2][ar] = a0.z; As[0][ak + 3][ar] = a0.w;
        As[0][ak + 4][ar] = a1.x; As[0][ak + 5][ar] = a1.y;
        As[0][ak + 6][ar] = a1.z; As[0][ak + 7][ar] = a1.w;
        float sc = g_sc[b * CH + br];
        float sh = g_sh[b * CH + br];
        float4 v = *(const float4*)(X + (size_t)br * HW + i0 + bc);
        v.x = v.x * sc + sh; v.y = v.y * sc + sh;
        v.z = v.z * sc + sh; v.w = v.w * sc + sh;
        *(float4*)&Bs[0][br][bc] = v;
    }
    __syncthreads();

    int buf = 0;
    for (int k0 = 0; k0 < CH; k0 += 16) {
        float4 na0, na1, nb;
        float nsc = 0.f, nsh = 0.f;
        int nk = k0 + 16;
        if (nk < CH) {  // issue next-tile loads early (hide latency)
            na0 = *(const float4*)(Wq + (size_t)(o0 + ar) * CH + nk + ak);
            na1 = *(const float4*)(Wq + (size_t)(o0 + ar) * CH + nk + ak + 4);
            nsc = g_sc[b * CH + nk + br];
            nsh = g_sh[b * CH + nk + br];
            nb  = *(const float4*)(X + (size_t)(nk + br) * HW + i0 + bc);
        }

        #pragma unroll
        for (int kk = 0; kk < 16; kk++) {
            float a[8];
            #pragma unroll
            for (int r = 0; r < 8; r++) a[r] = As[buf][kk][ty * 8 + r];
            float4 bv = *(float4*)&Bs[buf][kk][tx * 4];
            float bb[4] = {bv.x, bv.y, bv.z, bv.w};
            #pragma unroll
            for (int r = 0; r < 8; r++)
                #pragma unroll
                for (int c = 0; c < 4; c++)
                    acc[r][c] += a[r] * bb[c];
        }

        if (nk < CH) {
            int nbuf = buf ^ 1;
            As[nbuf][ak + 0][ar] = na0.x; As[nbuf][ak + 1][ar] = na0.y;
            As[nbuf][ak + 2][ar] = na0.z; As[nbuf][ak + 3][ar] = na0.w;
            As[nbuf][ak + 4][ar] = na1.x; As[nbuf][ak + 5][ar] = na1.y;
            As[nbuf][ak + 6][ar] = na1.z; As[nbuf][ak + 7][ar] = na1.w;
            nb.x = nb.x * nsc + nsh; nb.y = nb.y * nsc + nsh;
            nb.z = nb.z * nsc + nsh; nb.w = nb.w * nsc + nsh;
            *(float4*)&Bs[nbuf][br][bc] = nb;
        }
        __syncthreads();
        buf ^= 1;
    }

    #pragma unroll
    for (int r = 0; r < 8; r++) {
        int o = o0 + ty * 8 + r;
        float bi = bq[o];
        float4 out;
        out.x = acc[r][0] + bi; out.y = acc[r][1] + bi;
        out.z = acc[r][2] + bi; out.w = acc[r][3] + bi;
        *(float4*)(Y + (size_t)o * HW + i0 + tx * 4) = out;
    }
}

// ---------------------------------------------------------------------------
// Fused flash attention, double-buffered K/V tiles:
// one CTA = 64 queries for one (b,h). Q pre-scaled by 1/sqrt(d) at load.
// Qs,Ks: [d][i]/[d][j]; Vs TRANSPOSED [j][d] (float4 reads in P*V).
// ---------------------------------------------------------------------------
#define VPAD 68   // row stride for Vs[j][d]; multiple of 4 keeps float4 aligned

__global__ void attn_kernel() {
    int it = blockIdx.x;          // i-tile (16)
    int bh = blockIdx.y;          // b*NH + h (128)
    int b = bh / NH, h = bh % NH;
    size_t base = (size_t)b * 3 * CH * HW + (size_t)h * HD * HW;
    const float* Q = g_qkv + base;
    const float* K = g_qkv + base + (size_t)CH * HW;
    const float* V = g_qkv + base + (size_t)2 * CH * HW;
    int i0 = it * 64;

    extern __shared__ float sm[];
    float* Qs  = sm;                       // [64][64]   (d, i)
    float* Ks0 = Qs  + 64 * 64;            // 2 x [64][64] (d, j)
    float* Vs0 = Ks0 + 2 * 64 * 64;        // 2 x [64][VPAD] (j, d) transposed
    float* Ps  = Vs0 + 2 * 64 * VPAD;      // [64][65]   (i, j)

    int tid = threadIdx.x;
    int tx = tid & 15, ty = tid >> 4;
    const float scale = 0.125f;   // 1/sqrt(64)

    // load Q tile, pre-scaled
    for (int i4 = tid * 4; i4 < 4096; i4 += 1024) {
        int d = i4 >> 6, ii = i4 & 63;
        float4 q4 = *(const float4*)(Q + (size_t)d * HW + i0 + ii);
        q4.x *= scale; q4.y *= scale; q4.z *= scale; q4.w *= scale;
        *(float4*)&Qs[d * 64 + ii] = q4;
    }
    // prologue: K/V tile 0 into buffer 0
    #pragma unroll
    for (int s = 0; s < 4; s++) {
        int i4 = tid * 4 + s * 1024;
        int d = i4 >> 6, jj = i4 & 63;
        *(float4*)&Ks0[d * 64 + jj] = *(const float4*)(K + (size_t)d * HW + jj);
    }
    #pragma unroll
    for (int s = 0; s < 16; s++) {
        int i = tid + s * 256;
        int d = i >> 6, jj = i & 63;
        Vs0[jj * VPAD + d] = V[(size_t)d * HW + jj];
    }

    float m[4], l[4], o[4][4];
    #pragma unroll
    for (int r = 0; r < 4; r++) {
        m[r] = -INFINITY; l[r] = 0.f;
        #pragma unroll
        for (int c = 0; c < 4; c++) o[r][c] = 0.f;
    }
    __syncthreads();

    int buf = 0;
    for (int jt = 0; jt < 16; jt++) {
        const float* Kb = Ks0 + buf * 4096;
        const float* Vb = Vs0 + buf * 64 * VPAD;

        // prefetch next j-tile into registers (overlaps with compute below)
        float4 pk[4];
        float  pv[16];
        if (jt < 15) {
            int nj0 = (jt + 1) * 64;
            #pragma unroll
            for (int s = 0; s < 4; s++) {
                int i4 = tid * 4 + s * 1024;
                int d = i4 >> 6, jj = i4 & 63;
                pk[s] = *(const float4*)(K + (size_t)d * HW + nj0 + jj);
            }
            #pragma unroll
            for (int s = 0; s < 16; s++) {
                int i = tid + s * 256;
                int d = i >> 6, jj = i & 63;
                pv[s] = V[(size_t)d * HW + nj0 + jj];
            }
        }

        // S = Qs^T Kb  (4x4 per thread; scale already folded into Q)
        float s[4][4] = {};
        #pragma unroll 8
        for (int d = 0; d < 64; d++) {
            float4 qv = *(float4*)&Qs[d * 64 + ty * 4];
            const float4 kv = *(const float4*)&Kb[d * 64 + tx * 4];
            float qa[4] = {qv.x, qv.y, qv.z, qv.w};
            float ka[4] = {kv.x, kv.y, kv.z, kv.w};
            #pragma unroll
            for (int r = 0; r < 4; r++)
                #pragma unroll
                for (int c = 0; c < 4; c++)
                    s[r][c] += qa[r] * ka[c];
        }

        // online softmax (row = i, owned by the 16 threads sharing ty)
        float corr[4];
        #pragma unroll
        for (int r = 0; r < 4; r++) {
            float rm = fmaxf(fmaxf(s[r][0], s[r][1]), fmaxf(s[r][2], s[r][3]));
            #pragma unroll
            for (int msk = 1; msk < 16; msk <<= 1)
                rm = fmaxf(rm, __shfl_xor_sync(0xffffffffu, rm, msk));
            float mn = fmaxf(m[r], rm);
            corr[r] = __expf(m[r] - mn);
            float rsum = 0.f;
            #pragma unroll
            for (int c = 0; c < 4; c++) {
                s[r][c] = __expf(s[r][c] - mn);
                rsum += s[r][c];
            }
            #pragma unroll
            for (int msk = 1; msk < 16; msk <<= 1)
                rsum += __shfl_xor_sync(0xffffffffu, rsum, msk);
            l[r] = l[r] * corr[r] + rsum;
            m[r] = mn;
        }
        // write P to smem
        #pragma unroll
        for (int r = 0; r < 4; r++)
            #pragma unroll
            for (int c = 0; c < 4; c++)
                Ps[(ty * 4 + r) * 65 + tx * 4 + c] = s[r][c];
        __syncthreads();   // Ps visible; everyone done with prior buffers

        // rescale accumulators, then O += P * V   (o[i][d])
        #pragma unroll
        for (int r = 0; r < 4; r++)
            #pragma unroll
            for (int c = 0; c < 4; c++)
                o[r][c] *= corr[r];
        #pragma unroll 4
        for (int j = 0; j < 64; j++) {
            float p[4];
            #pragma unroll
            for (int r = 0; r < 4; r++) p[r] = Ps[(ty * 4 + r) * 65 + j];
            float4 vv = *(const float4*)&Vb[j * VPAD + tx * 4];
            float v[4] = {vv.x, vv.y, vv.z, vv.w};
            #pragma unroll
            for (int r = 0; r < 4; r++)
                #pragma unroll
                for (int c = 0; c < 4; c++)
                    o[r][c] += p[r] * v[c];
        }

        // drain prefetch into the alternate buffers
        if (jt < 15) {
            float* Kn = Ks0 + (buf ^ 1) * 4096;
            float* Vn = Vs0 + (buf ^ 1) * 64 * VPAD;
            #pragma unroll
            for (int s2 = 0; s2 < 4; s2++) {
                int i4 = tid * 4 + s2 * 1024;
                int d = i4 >> 6, jj = i4 & 63;
                *(float4*)&Kn[d * 64 + jj] = pk[s2];
            }
            #pragma unroll
            for (int s2 = 0; s2 < 16; s2++) {
                int i = tid + s2 * 256;
                int d = i >> 6, jj = i & 63;
                Vn[jj * VPAD + d] = pv[s2];
            }
        }
        __syncthreads();   // next buffers ready; Ps free for rewrite
        buf ^= 1;
    }

    // finalize: divide by l, stage through smem ([d][i], stride 65), write coalesced
    float invl[4];
    #pragma unroll
    for (int r = 0; r < 4; r++) invl[r] = 1.0f / l[r];
    #pragma unroll
    for (int r = 0; r < 4; r++)
        #pragma unroll
        for (int c = 0; c < 4; c++)
            Ps[(tx * 4 + c) * 65 + ty * 4 + r] = o[r][c] * invl[r];
    __syncthreads();

    float* O = g_atto + (size_t)b * CH * HW + (size_t)h * HD * HW;
    for (int i = tid; i < 4096; i += 256) {
        int d = i >> 6, ii = i & 63;
        O[(size_t)d * HW + i0 + ii] = Ps[d * 65 + ii];
    }
}

// ---------------------------------------------------------------------------
// Proj GEMM with fused residual, 2-stage smem pipeline:
//   out[b][o][i] = atto[b][o][i] + bp[o] + sum_k Wp[o][k] * atto[b][k][i]
// M=512, N=1024, K=512 per batch. Tile 128x64x16, 8x4 per thread.
// ---------------------------------------------------------------------------
__global__ void proj_gemm(const float* __restrict__ Wp,
                          const float* __restrict__ bp,
                          float* __restrict__ out) {
    int b  = blockIdx.z;
    int o0 = blockIdx.y * 128;
    int i0 = blockIdx.x * 64;
    const float* X = g_atto + (size_t)b * CH * HW;
    float*       Y = out    + (size_t)b * CH * HW;

    __shared__ float As[2][16][132];
    __shared__ float Bs[2][16][64];

    int tid = threadIdx.x;
    int tx = tid & 15, ty = tid >> 4;
    int ar = tid >> 1;
    int ak = (tid & 1) * 8;
    int br = tid >> 4;
    int bc = (tid & 15) * 4;
    float acc[8][4] = {};

    {
        float4 a0 = *(const float4*)(Wp + (size_t)(o0 + ar) * CH + ak);
        float4 a1 = *(const float4*)(Wp + (size_t)(o0 + ar) * CH + ak + 4);
        As[0][ak + 0][ar] = a0.x; As[0][ak + 1][ar] = a0.y;
        As[0][ak + 2][ar] = a0.z; As[0][ak + 3][ar] = a0.w;
        As[0][ak + 4][ar] = a1.x; As[0][ak + 5][ar] = a1.y;
        As[0][ak + 6][ar] = a1.z; As[0][ak + 7][ar] = a1.w;
        *(float4*)&Bs[0][br][bc] = *(const float4*)(X + (size_t)br * HW + i0 + bc);
    }
    __syncthreads();

    int buf = 0;
    for (int k0 = 0; k0 < CH; k0 += 16) {
        float4 na0, na1, nb;
        int nk = k0 + 16;
        if (nk < CH) {
            na0 = *(const float4*)(Wp + (size_t)(o0 + ar) * CH + nk + ak);
            na1 = *(const float4*)(Wp + (size_t)(o0 + ar) * CH + nk + ak + 4);
            nb  = *(const float4*)(X + (size_t)(nk + br) * HW + i0 + bc);
        }

        #pragma unroll
        for (int kk = 0; kk < 16; kk++) {
            float a[8];
            #pragma unroll
            for (int r = 0; r < 8; r++) a[r] = As[buf][kk][ty * 8 + r];
            float4 bv = *(float4*)&Bs[buf][kk][tx * 4];
            float bb[4] = {bv.x, bv.y, bv.z, bv.w};
            #pragma unroll
            for (int r = 0; r < 8; r++)
                #pragma unroll
                for (int c = 0; c < 4; c++)
                    acc[r][c] += a[r] * bb[c];
        }

        if (nk < CH) {
            int nbuf = buf ^ 1;
            As[nbuf][ak + 0][ar] = na0.x; As[nbuf][ak + 1][ar] = na0.y;
            As[nbuf][ak + 2][ar] = na0.z; As[nbuf][ak + 3][ar] = na0.w;
            As[nbuf][ak + 4][ar] = na1.x; As[nbuf][ak + 5][ar] = na1.y;
            As[nbuf][ak + 6][ar] = na1.z; As[nbuf][ak + 7][ar] = na1.w;
            *(float4*)&Bs[nbuf][br][bc] = nb;
        }
        __syncthreads();
        buf ^= 1;
    }

    #pragma unroll
    for (int r = 0; r < 8; r++) {
        int o = o0 + ty * 8 + r;
        float bi = bp[o];
        float4 res = *(const float4*)(X + (size_t)o * HW + i0 + tx * 4);
        float4 outv;
        outv.x = res.x + acc[r][0] + bi;
        outv.y = res.y + acc[r][1] + bi;
        outv.z = res.z + acc[r][2] + bi;
        outv.w = res.w + acc[r][3] + bi;
        *(float4*)(Y + (size_t)o * HW + i0 + tx * 4) = outv;
    }
}

// ---------------------------------------------------------------------------
extern "C" void kernel_launch(void* const* d_in, const int* in_sizes, int n_in,
                              void* d_out, int out_size) {
    const float* x      = (const float*)d_in[0];
    const float* gn_w   = (const float*)d_in[1];
    const float* gn_b   = (const float*)d_in[2];
    const float* qkv_w  = (const float*)d_in[3];
    const float* qkv_b  = (const float*)d_in[4];
    const float* proj_w = (const float*)d_in[5];
    const float* proj_b = (const float*)d_in[6];
    float* out = (float*)d_out;

    gn_stats<<<BATCH * NG, 256>>>(x, gn_w, gn_b);
    qkv_gemm<<<dim3(HW / 64, 3 * CH / 128, BATCH), 256>>>(x, qkv_w, qkv_b);

    int attn_smem = (64 * 64 + 2 * 64 * 64 + 2 * 64 * VPAD + 64 * 65)
                    * (int)sizeof(float);   // 100,608 bytes
    cudaFuncSetAttribute(attn_kernel, cudaFuncAttributeMaxDynamicSharedMemorySize,
                         attn_smem);
    attn_kernel<<<dim3(HW / 64, BATCH * NH), 256, attn_smem>>>();

    proj_gemm<<<dim3(HW / 64, CH / 128, BATCH), 256>>>(proj_w, proj_b, out);
}

// round 9
// speedup vs baseline: 1.0693x; 1.0693x over previous
#include <cuda_runtime.h>
#include <math.h>

#define BATCH 16
#define CH    512
#define HW    1024
#define NH    8
#define HD    64
#define NG    8
#define EPSV  1e-5f

// Scratch (allocation-free rule: __device__ globals)
__device__ float g_qkv [BATCH * 3 * CH * HW];      // 100.7 MB
__device__ float g_atto[BATCH * CH * HW];          // 33.5 MB
__device__ float g_sc  [BATCH * CH];               // per-(b,c) GN scale
__device__ float g_sh  [BATCH * CH];               // per-(b,c) GN shift

// ---------------------------------------------------------------------------
// GroupNorm stats only: one CTA per (b, g). Writes per-channel scale/shift.
// ---------------------------------------------------------------------------
__global__ void gn_stats(const float* __restrict__ x,
                         const float* __restrict__ w,
                         const float* __restrict__ bias) {
    const int GROUP = (CH / NG) * HW;   // 65536
    int bg = blockIdx.x;
    int b = bg / NG, g = bg % NG;
    const float* xp = x + (size_t)b * CH * HW + (size_t)g * (CH / NG) * HW;
    int tid = threadIdx.x;

    float s = 0.f, s2 = 0.f;
    for (int i = tid * 4; i < GROUP; i += blockDim.x * 4) {
        float4 v = *(const float4*)(xp + i);
        s  += v.x + v.y + v.z + v.w;
        s2 += v.x * v.x + v.y * v.y + v.z * v.z + v.w * v.w;
    }
    __shared__ float rs[256], rs2[256];
    rs[tid] = s; rs2[tid] = s2;
    __syncthreads();
    for (int o = 128; o > 0; o >>= 1) {
        if (tid < o) { rs[tid] += rs[tid + o]; rs2[tid] += rs2[tid + o]; }
        __syncthreads();
    }
    float mu  = rs[0]  * (1.0f / GROUP);
    float var = rs2[0] * (1.0f / GROUP) - mu * mu;
    float inv = rsqrtf(var + EPSV);

    if (tid < CH / NG) {
        int c = g * (CH / NG) + tid;
        float sc = w[c] * inv;
        g_sc[b * CH + c] = sc;
        g_sh[b * CH + c] = bias[c] - mu * sc;
    }
}

// ---------------------------------------------------------------------------
// QKV GEMM with fused GroupNorm on the B operand, 2-stage smem pipeline.
// Tile 128x128x16, 8x8 per thread (1.0 B/FMA smem traffic), 256 threads.
//   qkv[b][o][i] = sum_k W[o][k] * (x[b][k][i]*sc[b][k]+sh[b][k]) + bq[o]
// ---------------------------------------------------------------------------
__global__ void __launch_bounds__(256, 2)
qkv_gemm(const float* __restrict__ x,
         const float* __restrict__ Wq,
         const float* __restrict__ bq) {
    int b  = blockIdx.z;
    int o0 = blockIdx.y * 128;
    int i0 = blockIdx.x * 128;
    const float* X = x     + (size_t)b * CH * HW;
    float*       Y = g_qkv + (size_t)b * 3 * CH * HW;

    __shared__ float As[2][16][132];   // [stage][k][o]
    __shared__ float Bs[2][16][128];   // [stage][k][i]

    int tid = threadIdx.x;
    int tx = tid & 15, ty = tid >> 4;
    int ar = tid >> 1;                 // A-row this thread loads (0..127)
    int ak = (tid & 1) * 8;            // A k-offset
    int br = tid >> 4;                 // B k-row this thread loads (0..15)
    int bc = (tid & 15) * 4;           // B col (first half; second at +64)
    float acc[8][8] = {};

    // prologue: stage 0
    {
        float4 a0 = *(const float4*)(Wq + (size_t)(o0 + ar) * CH + ak);
        float4 a1 = *(const float4*)(Wq + (size_t)(o0 + ar) * CH + ak + 4);
        As[0][ak + 0][ar] = a0.x; As[0][ak + 1][ar] = a0.y;
        As[0][ak + 2][ar] = a0.z; As[0][ak + 3][ar] = a0.w;
        As[0][ak + 4][ar] = a1.x; As[0][ak + 5][ar] = a1.y;
        As[0][ak + 6][ar] = a1.z; As[0][ak + 7][ar] = a1.w;
        float sc = g_sc[b * CH + br];
        float sh = g_sh[b * CH + br];
        float4 v0 = *(const float4*)(X + (size_t)br * HW + i0 + bc);
        float4 v1 = *(const float4*)(X + (size_t)br * HW + i0 + bc + 64);
        v0.x = v0.x * sc + sh; v0.y = v0.y * sc + sh;
        v0.z = v0.z * sc + sh; v0.w = v0.w * sc + sh;
        v1.x = v1.x * sc + sh; v1.y = v1.y * sc + sh;
        v1.z = v1.z * sc + sh; v1.w = v1.w * sc + sh;
        *(float4*)&Bs[0][br][bc]      = v0;
        *(float4*)&Bs[0][br][bc + 64] = v1;
    }
    __syncthreads();

    int buf = 0;
    for (int k0 = 0; k0 < CH; k0 += 16) {
        float4 na0, na1, nb0, nb1;
        float nsc = 0.f, nsh = 0.f;
        int nk = k0 + 16;
        if (nk < CH) {  // issue next-tile loads early (hide latency)
            na0 = *(const float4*)(Wq + (size_t)(o0 + ar) * CH + nk + ak);
            na1 = *(const float4*)(Wq + (size_t)(o0 + ar) * CH + nk + ak + 4);
            nsc = g_sc[b * CH + nk + br];
            nsh = g_sh[b * CH + nk + br];
            nb0 = *(const float4*)(X + (size_t)(nk + br) * HW + i0 + bc);
            nb1 = *(const float4*)(X + (size_t)(nk + br) * HW + i0 + bc + 64);
        }

        #pragma unroll
        for (int kk = 0; kk < 16; kk++) {
            float a[8], bb[8];
            float4 av0 = *(float4*)&As[buf][kk][ty * 8];
            float4 av1 = *(float4*)&As[buf][kk][ty * 8 + 4];
            a[0] = av0.x; a[1] = av0.y; a[2] = av0.z; a[3] = av0.w;
            a[4] = av1.x; a[5] = av1.y; a[6] = av1.z; a[7] = av1.w;
            float4 bv0 = *(float4*)&Bs[buf][kk][tx * 4];
            float4 bv1 = *(float4*)&Bs[buf][kk][tx * 4 + 64];
            bb[0] = bv0.x; bb[1] = bv0.y; bb[2] = bv0.z; bb[3] = bv0.w;
            bb[4] = bv1.x; bb[5] = bv1.y; bb[6] = bv1.z; bb[7] = bv1.w;
            #pragma unroll
            for (int r = 0; r < 8; r++)
                #pragma unroll
                for (int c = 0; c < 8; c++)
                    acc[r][c] += a[r] * bb[c];
        }

        if (nk < CH) {
            int nbuf = buf ^ 1;
            As[nbuf][ak + 0][ar] = na0.x; As[nbuf][ak + 1][ar] = na0.y;
            As[nbuf][ak + 2][ar] = na0.z; As[nbuf][ak + 3][ar] = na0.w;
            As[nbuf][ak + 4][ar] = na1.x; As[nbuf][ak + 5][ar] = na1.y;
            As[nbuf][ak + 6][ar] = na1.z; As[nbuf][ak + 7][ar] = na1.w;
            nb0.x = nb0.x * nsc + nsh; nb0.y = nb0.y * nsc + nsh;
            nb0.z = nb0.z * nsc + nsh; nb0.w = nb0.w * nsc + nsh;
            nb1.x = nb1.x * nsc + nsh; nb1.y = nb1.y * nsc + nsh;
            nb1.z = nb1.z * nsc + nsh; nb1.w = nb1.w * nsc + nsh;
            *(float4*)&Bs[nbuf][br][bc]      = nb0;
            *(float4*)&Bs[nbuf][br][bc + 64] = nb1;
        }
        __syncthreads();
        buf ^= 1;
    }

    #pragma unroll
    for (int r = 0; r < 8; r++) {
        int o = o0 + ty * 8 + r;
        float bi = bq[o];
        float4 o0v, o1v;
        o0v.x = acc[r][0] + bi; o0v.y = acc[r][1] + bi;
        o0v.z = acc[r][2] + bi; o0v.w = acc[r][3] + bi;
        o1v.x = acc[r][4] + bi; o1v.y = acc[r][5] + bi;
        o1v.z = acc[r][6] + bi; o1v.w = acc[r][7] + bi;
        *(float4*)(Y + (size_t)o * HW + i0 + tx * 4)      = o0v;
        *(float4*)(Y + (size_t)o * HW + i0 + tx * 4 + 64) = o1v;
    }
}

// ---------------------------------------------------------------------------
// Fused flash attention, double-buffered K/V tiles:
// one CTA = 64 queries for one (b,h). Q pre-scaled by 1/sqrt(d) at load.
// Qs,Ks: [d][i]/[d][j]; Vs TRANSPOSED [j][d] (float4 reads in P*V).
// ---------------------------------------------------------------------------
#define VPAD 68   // row stride for Vs[j][d]; multiple of 4 keeps float4 aligned

__global__ void attn_kernel() {
    int it = blockIdx.x;          // i-tile (16)
    int bh = blockIdx.y;          // b*NH + h (128)
    int b = bh / NH, h = bh % NH;
    size_t base = (size_t)b * 3 * CH * HW + (size_t)h * HD * HW;
    const float* Q = g_qkv + base;
    const float* K = g_qkv + base + (size_t)CH * HW;
    const float* V = g_qkv + base + (size_t)2 * CH * HW;
    int i0 = it * 64;

    extern __shared__ float sm[];
    float* Qs  = sm;                       // [64][64]   (d, i)
    float* Ks0 = Qs  + 64 * 64;            // 2 x [64][64] (d, j)
    float* Vs0 = Ks0 + 2 * 64 * 64;        // 2 x [64][VPAD] (j, d) transposed
    float* Ps  = Vs0 + 2 * 64 * VPAD;      // [64][65]   (i, j)

    int tid = threadIdx.x;
    int tx = tid & 15, ty = tid >> 4;
    const float scale = 0.125f;   // 1/sqrt(64)

    // load Q tile, pre-scaled
    for (int i4 = tid * 4; i4 < 4096; i4 += 1024) {
        int d = i4 >> 6, ii = i4 & 63;
        float4 q4 = *(const float4*)(Q + (size_t)d * HW + i0 + ii);
        q4.x *= scale; q4.y *= scale; q4.z *= scale; q4.w *= scale;
        *(float4*)&Qs[d * 64 + ii] = q4;
    }
    // prologue: K/V tile 0 into buffer 0
    #pragma unroll
    for (int s = 0; s < 4; s++) {
        int i4 = tid * 4 + s * 1024;
        int d = i4 >> 6, jj = i4 & 63;
        *(float4*)&Ks0[d * 64 + jj] = *(const float4*)(K + (size_t)d * HW + jj);
    }
    #pragma unroll
    for (int s = 0; s < 16; s++) {
        int i = tid + s * 256;
        int d = i >> 6, jj = i & 63;
        Vs0[jj * VPAD + d] = V[(size_t)d * HW + jj];
    }

    float m[4], l[4], o[4][4];
    #pragma unroll
    for (int r = 0; r < 4; r++) {
        m[r] = -INFINITY; l[r] = 0.f;
        #pragma unroll
        for (int c = 0; c < 4; c++) o[r][c] = 0.f;
    }
    __syncthreads();

    int buf = 0;
    for (int jt = 0; jt < 16; jt++) {
        const float* Kb = Ks0 + buf * 4096;
        const float* Vb = Vs0 + buf * 64 * VPAD;

        // prefetch next j-tile into registers (overlaps with compute below)
        float4 pk[4];
        float  pv[16];
        if (jt < 15) {
            int nj0 = (jt + 1) * 64;
            #pragma unroll
            for (int s = 0; s < 4; s++) {
                int i4 = tid * 4 + s * 1024;
                int d = i4 >> 6, jj = i4 & 63;
                pk[s] = *(const float4*)(K + (size_t)d * HW + nj0 + jj);
            }
            #pragma unroll
            for (int s = 0; s < 16; s++) {
                int i = tid + s * 256;
                int d = i >> 6, jj = i & 63;
                pv[s] = V[(size_t)d * HW + nj0 + jj];
            }
        }

        // S = Qs^T Kb  (4x4 per thread; scale already folded into Q)
        float s[4][4] = {};
        #pragma unroll 8
        for (int d = 0; d < 64; d++) {
            float4 qv = *(float4*)&Qs[d * 64 + ty * 4];
            const float4 kv = *(const float4*)&Kb[d * 64 + tx * 4];
            float qa[4] = {qv.x, qv.y, qv.z, qv.w};
            float ka[4] = {kv.x, kv.y, kv.z, kv.w};
            #pragma unroll
            for (int r = 0; r < 4; r++)
                #pragma unroll
                for (int c = 0; c < 4; c++)
                    s[r][c] += qa[r] * ka[c];
        }

        // online softmax (row = i, owned by the 16 threads sharing ty)
        float corr[4];
        #pragma unroll
        for (int r = 0; r < 4; r++) {
            float rm = fmaxf(fmaxf(s[r][0], s[r][1]), fmaxf(s[r][2], s[r][3]));
            #pragma unroll
            for (int msk = 1; msk < 16; msk <<= 1)
                rm = fmaxf(rm, __shfl_xor_sync(0xffffffffu, rm, msk));
            float mn = fmaxf(m[r], rm);
            corr[r] = __expf(m[r] - mn);
            float rsum = 0.f;
            #pragma unroll
            for (int c = 0; c < 4; c++) {
                s[r][c] = __expf(s[r][c] - mn);
                rsum += s[r][c];
            }
            #pragma unroll
            for (int msk = 1; msk < 16; msk <<= 1)
                rsum += __shfl_xor_sync(0xffffffffu, rsum, msk);
            l[r] = l[r] * corr[r] + rsum;
            m[r] = mn;
        }
        // write P to smem
        #pragma unroll
        for (int r = 0; r < 4; r++)
            #pragma unroll
            for (int c = 0; c < 4; c++)
                Ps[(ty * 4 + r) * 65 + tx * 4 + c] = s[r][c];
        __syncthreads();   // Ps visible; everyone done with prior buffers

        // rescale accumulators, then O += P * V   (o[i][d])
        #pragma unroll
        for (int r = 0; r < 4; r++)
            #pragma unroll
            for (int c = 0; c < 4; c++)
                o[r][c] *= corr[r];
        #pragma unroll 4
        for (int j = 0; j < 64; j++) {
            float p[4];
            #pragma unroll
            for (int r = 0; r < 4; r++) p[r] = Ps[(ty * 4 + r) * 65 + j];
            float4 vv = *(const float4*)&Vb[j * VPAD + tx * 4];
            float v[4] = {vv.x, vv.y, vv.z, vv.w};
            #pragma unroll
            for (int r = 0; r < 4; r++)
                #pragma unroll
                for (int c = 0; c < 4; c++)
                    o[r][c] += p[r] * v[c];
        }

        // drain prefetch into the alternate buffers
        if (jt < 15) {
            float* Kn = Ks0 + (buf ^ 1) * 4096;
            float* Vn = Vs0 + (buf ^ 1) * 64 * VPAD;
            #pragma unroll
            for (int s2 = 0; s2 < 4; s2++) {
                int i4 = tid * 4 + s2 * 1024;
                int d = i4 >> 6, jj = i4 & 63;
                *(float4*)&Kn[d * 64 + jj] = pk[s2];
            }
            #pragma unroll
            for (int s2 = 0; s2 < 16; s2++) {
                int i = tid + s2 * 256;
                int d = i >> 6, jj = i & 63;
                Vn[jj * VPAD + d] = pv[s2];
            }
        }
        __syncthreads();   // next buffers ready; Ps free for rewrite
        buf ^= 1;
    }

    // finalize: divide by l, stage through smem ([d][i], stride 65), write coalesced
    float invl[4];
    #pragma unroll
    for (int r = 0; r < 4; r++) invl[r] = 1.0f / l[r];
    #pragma unroll
    for (int r = 0; r < 4; r++)
        #pragma unroll
        for (int c = 0; c < 4; c++)
            Ps[(tx * 4 + c) * 65 + ty * 4 + r] = o[r][c] * invl[r];
    __syncthreads();

    float* O = g_atto + (size_t)b * CH * HW + (size_t)h * HD * HW;
    for (int i = tid; i < 4096; i += 256) {
        int d = i >> 6, ii = i & 63;
        O[(size_t)d * HW + i0 + ii] = Ps[d * 65 + ii];
    }
}

// ---------------------------------------------------------------------------
// Proj GEMM with fused residual, 2-stage smem pipeline.
// Tile 128x128x16, 8x8 per thread, 256 threads.
//   out[b][o][i] = atto[b][o][i] + bp[o] + sum_k Wp[o][k] * atto[b][k][i]
// ---------------------------------------------------------------------------
__global__ void __launch_bounds__(256, 2)
proj_gemm(const float* __restrict__ Wp,
          const float* __restrict__ bp,
          float* __restrict__ out) {
    int b  = blockIdx.z;
    int o0 = blockIdx.y * 128;
    int i0 = blockIdx.x * 128;
    const float* X = g_atto + (size_t)b * CH * HW;
    float*       Y = out    + (size_t)b * CH * HW;

    __shared__ float As[2][16][132];
    __shared__ float Bs[2][16][128];

    int tid = threadIdx.x;
    int tx = tid & 15, ty = tid >> 4;
    int ar = tid >> 1;
    int ak = (tid & 1) * 8;
    int br = tid >> 4;
    int bc = (tid & 15) * 4;
    float acc[8][8] = {};

    {
        float4 a0 = *(const float4*)(Wp + (size_t)(o0 + ar) * CH + ak);
        float4 a1 = *(const float4*)(Wp + (size_t)(o0 + ar) * CH + ak + 4);
        As[0][ak + 0][ar] = a0.x; As[0][ak + 1][ar] = a0.y;
        As[0][ak + 2][ar] = a0.z; As[0][ak + 3][ar] = a0.w;
        As[0][ak + 4][ar] = a1.x; As[0][ak + 5][ar] = a1.y;
        As[0][ak + 6][ar] = a1.z; As[0][ak + 7][ar] = a1.w;
        *(float4*)&Bs[0][br][bc]      = *(const float4*)(X + (size_t)br * HW + i0 + bc);
        *(float4*)&Bs[0][br][bc + 64] = *(const float4*)(X + (size_t)br * HW + i0 + bc + 64);
    }
    __syncthreads();

    int buf = 0;
    for (int k0 = 0; k0 < CH; k0 += 16) {
        float4 na0, na1, nb0, nb1;
        int nk = k0 + 16;
        if (nk < CH) {
            na0 = *(const float4*)(Wp + (size_t)(o0 + ar) * CH + nk + ak);
            na1 = *(const float4*)(Wp + (size_t)(o0 + ar) * CH + nk + ak + 4);
            nb0 = *(const float4*)(X + (size_t)(nk + br) * HW + i0 + bc);
            nb1 = *(const float4*)(X + (size_t)(nk + br) * HW + i0 + bc + 64);
        }

        #pragma unroll
        for (int kk = 0; kk < 16; kk++) {
            float a[8], bb[8];
            float4 av0 = *(float4*)&As[buf][kk][ty * 8];
            float4 av1 = *(float4*)&As[buf][kk][ty * 8 + 4];
            a[0] = av0.x; a[1] = av0.y; a[2] = av0.z; a[3] = av0.w;
            a[4] = av1.x; a[5] = av1.y; a[6] = av1.z; a[7] = av1.w;
            float4 bv0 = *(float4*)&Bs[buf][kk][tx * 4];
            float4 bv1 = *(float4*)&Bs[buf][kk][tx * 4 + 64];
            bb[0] = bv0.x; bb[1] = bv0.y; bb[2] = bv0.z; bb[3] = bv0.w;
            bb[4] = bv1.x; bb[5] = bv1.y; bb[6] = bv1.z; bb[7] = bv1.w;
            #pragma unroll
            for (int r = 0; r < 8; r++)
                #pragma unroll
                for (int c = 0; c < 8; c++)
                    acc[r][c] += a[r] * bb[c];
        }

        if (nk < CH) {
            int nbuf = buf ^ 1;
            As[nbuf][ak + 0][ar] = na0.x; As[nbuf][ak + 1][ar] = na0.y;
            As[nbuf][ak + 2][ar] = na0.z; As[nbuf][ak + 3][ar] = na0.w;
            As[nbuf][ak + 4][ar] = na1.x; As[nbuf][ak + 5][ar] = na1.y;
            As[nbuf][ak + 6][ar] = na1.z; As[nbuf][ak + 7][ar] = na1.w;
            *(float4*)&Bs[nbuf][br][bc]      = nb0;
            *(float4*)&Bs[nbuf][br][bc + 64] = nb1;
        }
        __syncthreads();
        buf ^= 1;
    }

    #pragma unroll
    for (int r = 0; r < 8; r++) {
        int o = o0 + ty * 8 + r;
        float bi = bp[o];
        float4 res0 = *(const float4*)(X + (size_t)o * HW + i0 + tx * 4);
        float4 res1 = *(const float4*)(X + (size_t)o * HW + i0 + tx * 4 + 64);
        float4 o0v, o1v;
        o0v.x = res0.x + acc[r][0] + bi; o0v.y = res0.y + acc[r][1] + bi;
        o0v.z = res0.z + acc[r][2] + bi; o0v.w = res0.w + acc[r][3] + bi;
        o1v.x = res1.x + acc[r][4] + bi; o1v.y = res1.y + acc[r][5] + bi;
        o1v.z = res1.z + acc[r][6] + bi; o1v.w = res1.w + acc[r][7] + bi;
        *(float4*)(Y + (size_t)o * HW + i0 + tx * 4)      = o0v;
        *(float4*)(Y + (size_t)o * HW + i0 + tx * 4 + 64) = o1v;
    }
}

// ---------------------------------------------------------------------------
extern "C" void kernel_launch(void* const* d_in, const int* in_sizes, int n_in,
                              void* d_out, int out_size) {
    const float* x      = (const float*)d_in[0];
    const float* gn_w   = (const float*)d_in[1];
    const float* gn_b   = (const float*)d_in[2];
    const float* qkv_w  = (const float*)d_in[3];
    const float* qkv_b  = (const float*)d_in[4];
    const float* proj_w = (const float*)d_in[5];
    const float* proj_b = (const float*)d_in[6];
    float* out = (float*)d_out;

    gn_stats<<<BATCH * NG, 256>>>(x, gn_w, gn_b);
    qkv_gemm<<<dim3(HW / 128, 3 * CH / 128, BATCH), 256>>>(x, qkv_w, qkv_b);

    int attn_smem = (64 * 64 + 2 * 64 * 64 + 2 * 64 * VPAD + 64 * 65)
                    * (int)sizeof(float);   // 100,608 bytes
    cudaFuncSetAttribute(attn_kernel, cudaFuncAttributeMaxDynamicSharedMemorySize,
                         attn_smem);
    attn_kernel<<<dim3(HW / 64, BATCH * NH), 256, attn_smem>>>();

    proj_gemm<<<dim3(HW / 128, CH / 128, BATCH), 256>>>(proj_w, proj_b, out);
}

// round 17
// speedup vs baseline: 1.0949x; 1.0240x over previous
#include <cuda_runtime.h>
#include <math.h>

#define BATCH 16
#define CH    512
#define HW    1024
#define NH    8
#define HD    64
#define NG    8
#define EPSV  1e-5f

// Scratch (allocation-free rule: __device__ globals)
__device__ float g_qkv [BATCH * 3 * CH * HW];      // 100.7 MB
__device__ float g_atto[BATCH * CH * HW];          // 33.5 MB
__device__ float g_sc  [BATCH * CH];               // per-(b,c) GN scale
__device__ float g_sh  [BATCH * CH];               // per-(b,c) GN shift

// ---------------------------------------------------------------------------
// GroupNorm stats only: one CTA per (b, g). Writes per-channel scale/shift.
// ---------------------------------------------------------------------------
__global__ void gn_stats(const float* __restrict__ x,
                         const float* __restrict__ w,
                         const float* __restrict__ bias) {
    const int GROUP = (CH / NG) * HW;   // 65536
    int bg = blockIdx.x;
    int b = bg / NG, g = bg % NG;
    const float* xp = x + (size_t)b * CH * HW + (size_t)g * (CH / NG) * HW;
    int tid = threadIdx.x;

    float s = 0.f, s2 = 0.f;
    for (int i = tid * 4; i < GROUP; i += blockDim.x * 4) {
        float4 v = *(const float4*)(xp + i);
        s  += v.x + v.y + v.z + v.w;
        s2 += v.x * v.x + v.y * v.y + v.z * v.z + v.w * v.w;
    }
    __shared__ float rs[256], rs2[256];
    rs[tid] = s; rs2[tid] = s2;
    __syncthreads();
    for (int o = 128; o > 0; o >>= 1) {
        if (tid < o) { rs[tid] += rs[tid + o]; rs2[tid] += rs2[tid + o]; }
        __syncthreads();
    }
    float mu  = rs[0]  * (1.0f / GROUP);
    float var = rs2[0] * (1.0f / GROUP) - mu * mu;
    float inv = rsqrtf(var + EPSV);

    if (tid < CH / NG) {
        int c = g * (CH / NG) + tid;
        float sc = w[c] * inv;
        g_sc[b * CH + c] = sc;
        g_sh[b * CH + c] = bias[c] - mu * sc;
    }
}

// ---------------------------------------------------------------------------
// QKV GEMM with fused GroupNorm on the B operand, 2-stage smem pipeline.
// Tile 128x128x16, 8x8 per thread, 256 threads.
//   qkv[b][o][i] = sum_k W[o][k] * (x[b][k][i]*sc[b][k]+sh[b][k]) + bq[o]
// ---------------------------------------------------------------------------
__global__ void __launch_bounds__(256, 2)
qkv_gemm(const float* __restrict__ x,
         const float* __restrict__ Wq,
         const float* __restrict__ bq) {
    int b  = blockIdx.z;
    int o0 = blockIdx.y * 128;
    int i0 = blockIdx.x * 128;
    const float* X = x     + (size_t)b * CH * HW;
    float*       Y = g_qkv + (size_t)b * 3 * CH * HW;

    __shared__ float As[2][16][132];   // [stage][k][o]
    __shared__ float Bs[2][16][128];   // [stage][k][i]

    int tid = threadIdx.x;
    int tx = tid & 15, ty = tid >> 4;
    int ar = tid >> 1;                 // A-row this thread loads (0..127)
    int ak = (tid & 1) * 8;            // A k-offset
    int br = tid >> 4;                 // B k-row this thread loads (0..15)
    int bc = (tid & 15) * 4;           // B col (first half; second at +64)
    float acc[8][8] = {};

    // prologue: stage 0
    {
        float4 a0 = *(const float4*)(Wq + (size_t)(o0 + ar) * CH + ak);
        float4 a1 = *(const float4*)(Wq + (size_t)(o0 + ar) * CH + ak + 4);
        As[0][ak + 0][ar] = a0.x; As[0][ak + 1][ar] = a0.y;
        As[0][ak + 2][ar] = a0.z; As[0][ak + 3][ar] = a0.w;
        As[0][ak + 4][ar] = a1.x; As[0][ak + 5][ar] = a1.y;
        As[0][ak + 6][ar] = a1.z; As[0][ak + 7][ar] = a1.w;
        float sc = g_sc[b * CH + br];
        float sh = g_sh[b * CH + br];
        float4 v0 = *(const float4*)(X + (size_t)br * HW + i0 + bc);
        float4 v1 = *(const float4*)(X + (size_t)br * HW + i0 + bc + 64);
        v0.x = v0.x * sc + sh; v0.y = v0.y * sc + sh;
        v0.z = v0.z * sc + sh; v0.w = v0.w * sc + sh;
        v1.x = v1.x * sc + sh; v1.y = v1.y * sc + sh;
        v1.z = v1.z * sc + sh; v1.w = v1.w * sc + sh;
        *(float4*)&Bs[0][br][bc]      = v0;
        *(float4*)&Bs[0][br][bc + 64] = v1;
    }
    __syncthreads();

    int buf = 0;
    for (int k0 = 0; k0 < CH; k0 += 16) {
        float4 na0, na1, nb0, nb1;
        float nsc = 0.f, nsh = 0.f;
        int nk = k0 + 16;
        if (nk < CH) {  // issue next-tile loads early (hide latency)
            na0 = *(const float4*)(Wq + (size_t)(o0 + ar) * CH + nk + ak);
            na1 = *(const float4*)(Wq + (size_t)(o0 + ar) * CH + nk + ak + 4);
            nsc = g_sc[b * CH + nk + br];
            nsh = g_sh[b * CH + nk + br];
            nb0 = *(const float4*)(X + (size_t)(nk + br) * HW + i0 + bc);
            nb1 = *(const float4*)(X + (size_t)(nk + br) * HW + i0 + bc + 64);
        }

        #pragma unroll
        for (int kk = 0; kk < 16; kk++) {
            float a[8], bb[8];
            float4 av0 = *(float4*)&As[buf][kk][ty * 8];
            float4 av1 = *(float4*)&As[buf][kk][ty * 8 + 4];
            a[0] = av0.x; a[1] = av0.y; a[2] = av0.z; a[3] = av0.w;
            a[4] = av1.x; a[5] = av1.y; a[6] = av1.z; a[7] = av1.w;
            float4 bv0 = *(float4*)&Bs[buf][kk][tx * 4];
            float4 bv1 = *(float4*)&Bs[buf][kk][tx * 4 + 64];
            bb[0] = bv0.x; bb[1] = bv0.y; bb[2] = bv0.z; bb[3] = bv0.w;
            bb[4] = bv1.x; bb[5] = bv1.y; bb[6] = bv1.z; bb[7] = bv1.w;
            #pragma unroll
            for (int r = 0; r < 8; r++)
                #pragma unroll
                for (int c = 0; c < 8; c++)
                    acc[r][c] += a[r] * bb[c];
        }

        if (nk < CH) {
            int nbuf = buf ^ 1;
            As[nbuf][ak + 0][ar] = na0.x; As[nbuf][ak + 1][ar] = na0.y;
            As[nbuf][ak + 2][ar] = na0.z; As[nbuf][ak + 3][ar] = na0.w;
            As[nbuf][ak + 4][ar] = na1.x; As[nbuf][ak + 5][ar] = na1.y;
            As[nbuf][ak + 6][ar] = na1.z; As[nbuf][ak + 7][ar] = na1.w;
            nb0.x = nb0.x * nsc + nsh; nb0.y = nb0.y * nsc + nsh;
            nb0.z = nb0.z * nsc + nsh; nb0.w = nb0.w * nsc + nsh;
            nb1.x = nb1.x * nsc + nsh; nb1.y = nb1.y * nsc + nsh;
            nb1.z = nb1.z * nsc + nsh; nb1.w = nb1.w * nsc + nsh;
            *(float4*)&Bs[nbuf][br][bc]      = nb0;
            *(float4*)&Bs[nbuf][br][bc + 64] = nb1;
        }
        __syncthreads();
        buf ^= 1;
    }

    #pragma unroll
    for (int r = 0; r < 8; r++) {
        int o = o0 + ty * 8 + r;
        float bi = bq[o];
        float4 o0v, o1v;
        o0v.x = acc[r][0] + bi; o0v.y = acc[r][1] + bi;
        o0v.z = acc[r][2] + bi; o0v.w = acc[r][3] + bi;
        o1v.x = acc[r][4] + bi; o1v.y = acc[r][5] + bi;
        o1v.z = acc[r][6] + bi; o1v.w = acc[r][7] + bi;
        *(float4*)(Y + (size_t)o * HW + i0 + tx * 4)      = o0v;
        *(float4*)(Y + (size_t)o * HW + i0 + tx * 4 + 64) = o1v;
    }
}

// ---------------------------------------------------------------------------
// Fused flash attention, double-buffered K/V tiles:
// one CTA = 64 queries for one (b,h). Q pre-scaled by 1/sqrt(d) at load.
// Qs,Ks: [d][i]/[d][j]; Vs TRANSPOSED [j][d]; Ps rows padded to 68 so the
// P*V loop reads P as float4 along j (2 LDS.128 per 16 FMA, was 5 LDS).
// ---------------------------------------------------------------------------
#define VPAD 68   // row stride for Vs[j][d]
#define PPAD 68   // row stride for Ps[i][j]; multiple of 4 -> aligned float4

__global__ void attn_kernel() {
    int it = blockIdx.x;          // i-tile (16)
    int bh = blockIdx.y;          // b*NH + h (128)
    int b = bh / NH, h = bh % NH;
    size_t base = (size_t)b * 3 * CH * HW + (size_t)h * HD * HW;
    const float* Q = g_qkv + base;
    const float* K = g_qkv + base + (size_t)CH * HW;
    const float* V = g_qkv + base + (size_t)2 * CH * HW;
    int i0 = it * 64;

    extern __shared__ float sm[];
    float* Qs  = sm;                       // [64][64]   (d, i)
    float* Ks0 = Qs  + 64 * 64;            // 2 x [64][64] (d, j)
    float* Vs0 = Ks0 + 2 * 64 * 64;        // 2 x [64][VPAD] (j, d) transposed
    float* Ps  = Vs0 + 2 * 64 * VPAD;      // [64][PPAD]  (i, j)

    int tid = threadIdx.x;
    int tx = tid & 15, ty = tid >> 4;
    const float scale = 0.125f;   // 1/sqrt(64)

    // load Q tile, pre-scaled
    for (int i4 = tid * 4; i4 < 4096; i4 += 1024) {
        int d = i4 >> 6, ii = i4 & 63;
        float4 q4 = *(const float4*)(Q + (size_t)d * HW + i0 + ii);
        q4.x *= scale; q4.y *= scale; q4.z *= scale; q4.w *= scale;
        *(float4*)&Qs[d * 64 + ii] = q4;
    }
    // prologue: K/V tile 0 into buffer 0
    #pragma unroll
    for (int s = 0; s < 4; s++) {
        int i4 = tid * 4 + s * 1024;
        int d = i4 >> 6, jj = i4 & 63;
        *(float4*)&Ks0[d * 64 + jj] = *(const float4*)(K + (size_t)d * HW + jj);
    }
    #pragma unroll
    for (int s = 0; s < 16; s++) {
        int i = tid + s * 256;
        int d = i >> 6, jj = i & 63;
        Vs0[jj * VPAD + d] = V[(size_t)d * HW + jj];
    }

    float m[4], l[4], o[4][4];
    #pragma unroll
    for (int r = 0; r < 4; r++) {
        m[r] = -INFINITY; l[r] = 0.f;
        #pragma unroll
        for (int c = 0; c < 4; c++) o[r][c] = 0.f;
    }
    __syncthreads();

    int buf = 0;
    for (int jt = 0; jt < 16; jt++) {
        const float* Kb = Ks0 + buf * 4096;
        const float* Vb = Vs0 + buf * 64 * VPAD;

        // prefetch next j-tile into registers (overlaps with compute below)
        float4 pk[4];
        float  pv[16];
        if (jt < 15) {
            int nj0 = (jt + 1) * 64;
            #pragma unroll
            for (int s = 0; s < 4; s++) {
                int i4 = tid * 4 + s * 1024;
                int d = i4 >> 6, jj = i4 & 63;
                pk[s] = *(const float4*)(K + (size_t)d * HW + nj0 + jj);
            }
            #pragma unroll
            for (int s = 0; s < 16; s++) {
                int i = tid + s * 256;
                int d = i >> 6, jj = i & 63;
                pv[s] = V[(size_t)d * HW + nj0 + jj];
            }
        }

        // S = Qs^T Kb  (4x4 per thread; scale already folded into Q)
        float s[4][4] = {};
        #pragma unroll 8
        for (int d = 0; d < 64; d++) {
            float4 qv = *(float4*)&Qs[d * 64 + ty * 4];
            const float4 kv = *(const float4*)&Kb[d * 64 + tx * 4];
            float qa[4] = {qv.x, qv.y, qv.z, qv.w};
            float ka[4] = {kv.x, kv.y, kv.z, kv.w};
            #pragma unroll
            for (int r = 0; r < 4; r++)
                #pragma unroll
                for (int c = 0; c < 4; c++)
                    s[r][c] += qa[r] * ka[c];
        }

        // online softmax (row = i, owned by the 16 threads sharing ty)
        float corr[4];
        #pragma unroll
        for (int r = 0; r < 4; r++) {
            float rm = fmaxf(fmaxf(s[r][0], s[r][1]), fmaxf(s[r][2], s[r][3]));
            #pragma unroll
            for (int msk = 1; msk < 16; msk <<= 1)
                rm = fmaxf(rm, __shfl_xor_sync(0xffffffffu, rm, msk));
            float mn = fmaxf(m[r], rm);
            corr[r] = __expf(m[r] - mn);
            float rsum = 0.f;
            #pragma unroll
            for (int c = 0; c < 4; c++) {
                s[r][c] = __expf(s[r][c] - mn);
                rsum += s[r][c];
            }
            #pragma unroll
            for (int msk = 1; msk < 16; msk <<= 1)
                rsum += __shfl_xor_sync(0xffffffffu, rsum, msk);
            l[r] = l[r] * corr[r] + rsum;
            m[r] = mn;
        }
        // write P to smem (P[i][j], row stride PPAD)
        #pragma unroll
        for (int r = 0; r < 4; r++)
            #pragma unroll
            for (int c = 0; c < 4; c++)
                Ps[(ty * 4 + r) * PPAD + tx * 4 + c] = s[r][c];
        __syncthreads();   // Ps visible; everyone done with prior buffers

        // rescale accumulators, then O += P * V   (o[i][d])
        // 4 j per step: p rows as float4 (1 LDS.128 each) + 4 V float4 reads
        #pragma unroll
        for (int r = 0; r < 4; r++)
            #pragma unroll
            for (int c = 0; c < 4; c++)
                o[r][c] *= corr[r];
        #pragma unroll 2
        for (int j4 = 0; j4 < 16; j4++) {
            float p[4][4];
            #pragma unroll
            for (int r = 0; r < 4; r++) {
                float4 p4 = *(float4*)&Ps[(ty * 4 + r) * PPAD + j4 * 4];
                p[r][0] = p4.x; p[r][1] = p4.y; p[r][2] = p4.z; p[r][3] = p4.w;
            }
            #pragma unroll
            for (int jj = 0; jj < 4; jj++) {
                float4 vv = *(const float4*)&Vb[(j4 * 4 + jj) * VPAD + tx * 4];
                float v[4] = {vv.x, vv.y, vv.z, vv.w};
                #pragma unroll
                for (int r = 0; r < 4; r++)
                    #pragma unroll
                    for (int c = 0; c < 4; c++)
                        o[r][c] += p[r][jj] * v[c];
            }
        }

        // drain prefetch into the alternate buffers
        if (jt < 15) {
            float* Kn = Ks0 + (buf ^ 1) * 4096;
            float* Vn = Vs0 + (buf ^ 1) * 64 * VPAD;
            #pragma unroll
            for (int s2 = 0; s2 < 4; s2++) {
                int i4 = tid * 4 + s2 * 1024;
                int d = i4 >> 6, jj = i4 & 63;
                *(float4*)&Kn[d * 64 + jj] = pk[s2];
            }
            #pragma unroll
            for (int s2 = 0; s2 < 16; s2++) {
                int i = tid + s2 * 256;
                int d = i >> 6, jj = i & 63;
                Vn[jj * VPAD + d] = pv[s2];
            }
        }
        __syncthreads();   // next buffers ready; Ps free for rewrite
        buf ^= 1;
    }

    // finalize: divide by l, stage through smem ([d][i], stride PPAD), write
    float invl[4];
    #pragma unroll
    for (int r = 0; r < 4; r++) invl[r] = 1.0f / l[r];
    #pragma unroll
    for (int r = 0; r < 4; r++)
        #pragma unroll
        for (int c = 0; c < 4; c++)
            Ps[(tx * 4 + c) * PPAD + ty * 4 + r] = o[r][c] * invl[r];
    __syncthreads();

    float* O = g_atto + (size_t)b * CH * HW + (size_t)h * HD * HW;
    for (int i = tid; i < 4096; i += 256) {
        int d = i >> 6, ii = i & 63;
        O[(size_t)d * HW + i0 + ii] = Ps[d * PPAD + ii];
    }
}

// ---------------------------------------------------------------------------
// Proj GEMM with fused residual, 2-stage smem pipeline.
// Tile 128x128x16, 8x8 per thread, 256 threads.
//   out[b][o][i] = atto[b][o][i] + bp[o] + sum_k Wp[o][k] * atto[b][k][i]
// ---------------------------------------------------------------------------
__global__ void __launch_bounds__(256, 2)
proj_gemm(const float* __restrict__ Wp,
          const float* __restrict__ bp,
          float* __restrict__ out) {
    int b  = blockIdx.z;
    int o0 = blockIdx.y * 128;
    int i0 = blockIdx.x * 128;
    const float* X = g_atto + (size_t)b * CH * HW;
    float*       Y = out    + (size_t)b * CH * HW;

    __shared__ float As[2][16][132];
    __shared__ float Bs[2][16][128];

    int tid = threadIdx.x;
    int tx = tid & 15, ty = tid >> 4;
    int ar = tid >> 1;
    int ak = (tid & 1) * 8;
    int br = tid >> 4;
    int bc = (tid & 15) * 4;
    float acc[8][8] = {};

    {
        float4 a0 = *(const float4*)(Wp + (size_t)(o0 + ar) * CH + ak);
        float4 a1 = *(const float4*)(Wp + (size_t)(o0 + ar) * CH + ak + 4);
        As[0][ak + 0][ar] = a0.x; As[0][ak + 1][ar] = a0.y;
        As[0][ak + 2][ar] = a0.z; As[0][ak + 3][ar] = a0.w;
        As[0][ak + 4][ar] = a1.x; As[0][ak + 5][ar] = a1.y;
        As[0][ak + 6][ar] = a1.z; As[0][ak + 7][ar] = a1.w;
        *(float4*)&Bs[0][br][bc]      = *(const float4*)(X + (size_t)br * HW + i0 + bc);
        *(float4*)&Bs[0][br][bc + 64] = *(const float4*)(X + (size_t)br * HW + i0 + bc + 64);
    }
    __syncthreads();

    int buf = 0;
    for (int k0 = 0; k0 < CH; k0 += 16) {
        float4 na0, na1, nb0, nb1;
        int nk = k0 + 16;
        if (nk < CH) {
            na0 = *(const float4*)(Wp + (size_t)(o0 + ar) * CH + nk + ak);
            na1 = *(const float4*)(Wp + (size_t)(o0 + ar) * CH + nk + ak + 4);
            nb0 = *(const float4*)(X + (size_t)(nk + br) * HW + i0 + bc);
            nb1 = *(const float4*)(X + (size_t)(nk + br) * HW + i0 + bc + 64);
        }

        #pragma unroll
        for (int kk = 0; kk < 16; kk++) {
            float a[8], bb[8];
            float4 av0 = *(float4*)&As[buf][kk][ty * 8];
            float4 av1 = *(float4*)&As[buf][kk][ty * 8 + 4];
            a[0] = av0.x; a[1] = av0.y; a[2] = av0.z; a[3] = av0.w;
            a[4] = av1.x; a[5] = av1.y; a[6] = av1.z; a[7] = av1.w;
            float4 bv0 = *(float4*)&Bs[buf][kk][tx * 4];
            float4 bv1 = *(float4*)&Bs[buf][kk][tx * 4 + 64];
            bb[0] = bv0.x; bb[1] = bv0.y; bb[2] = bv0.z; bb[3] = bv0.w;
            bb[4] = bv1.x; bb[5] = bv1.y; bb[6] = bv1.z; bb[7] = bv1.w;
            #pragma unroll
            for (int r = 0; r < 8; r++)
                #pragma unroll
                for (int c = 0; c < 8; c++)
                    acc[r][c] += a[r] * bb[c];
        }

        if (nk < CH) {
            int nbuf = buf ^ 1;
            As[nbuf][ak + 0][ar] = na0.x; As[nbuf][ak + 1][ar] = na0.y;
            As[nbuf][ak + 2][ar] = na0.z; As[nbuf][ak + 3][ar] = na0.w;
            As[nbuf][ak + 4][ar] = na1.x; As[nbuf][ak + 5][ar] = na1.y;
            As[nbuf][ak + 6][ar] = na1.z; As[nbuf][ak + 7][ar] = na1.w;
            *(float4*)&Bs[nbuf][br][bc]      = nb0;
            *(float4*)&Bs[nbuf][br][bc + 64] = nb1;
        }
        __syncthreads();
        buf ^= 1;
    }

    #pragma unroll
    for (int r = 0; r < 8; r++) {
        int o = o0 + ty * 8 + r;
        float bi = bp[o];
        float4 res0 = *(const float4*)(X + (size_t)o * HW + i0 + tx * 4);
        float4 res1 = *(const float4*)(X + (size_t)o * HW + i0 + tx * 4 + 64);
        float4 o0v, o1v;
        o0v.x = res0.x + acc[r][0] + bi; o0v.y = res0.y + acc[r][1] + bi;
        o0v.z = res0.z + acc[r][2] + bi; o0v.w = res0.w + acc[r][3] + bi;
        o1v.x = res1.x + acc[r][4] + bi; o1v.y = res1.y + acc[r][5] + bi;
        o1v.z = res1.z + acc[r][6] + bi; o1v.w = res1.w + acc[r][7] + bi;
        *(float4*)(Y + (size_t)o * HW + i0 + tx * 4)      = o0v;
        *(float4*)(Y + (size_t)o * HW + i0 + tx * 4 + 64) = o1v;
    }
}

// ---------------------------------------------------------------------------
extern "C" void kernel_launch(void* const* d_in, const int* in_sizes, int n_in,
                              void* d_out, int out_size) {
    const float* x      = (const float*)d_in[0];
    const float* gn_w   = (const float*)d_in[1];
    const float* gn_b   = (const float*)d_in[2];
    const float* qkv_w  = (const float*)d_in[3];
    const float* qkv_b  = (const float*)d_in[4];
    const float* proj_w = (const float*)d_in[5];
    const float* proj_b = (const float*)d_in[6];
    float* out = (float*)d_out;

    gn_stats<<<BATCH * NG, 256>>>(x, gn_w, gn_b);
    qkv_gemm<<<dim3(HW / 128, 3 * CH / 128, BATCH), 256>>>(x, qkv_w, qkv_b);

    int attn_smem = (64 * 64 + 2 * 64 * 64 + 2 * 64 * VPAD + 64 * PPAD)
                    * (int)sizeof(float);   // 101,376 bytes
    cudaFuncSetAttribute(attn_kernel, cudaFuncAttributeMaxDynamicSharedMemorySize,
                         attn_smem);
    attn_kernel<<<dim3(HW / 64, BATCH * NH), 256, attn_smem>>>();

    proj_gemm<<<dim3(HW / 128, CH / 128, BATCH), 256>>>(proj_w, proj_b, out);
}